// round 2
// baseline (speedup 1.0000x reference)
#include <cuda_runtime.h>
#include <cstdint>
#include <math.h>

#define N_NODES   100000
#define N_EDGES   200000
#define NNZ       2000000
#define DIM       64
#define HID       32
#define K_KEEP    1000000

// ---------------- device scratch (no allocations allowed) ----------------
struct Ctrl {
    unsigned p1, p2, Tbits;
    int rank;
    int skip;
    int ib;
    int cutoff;
};

__device__ __align__(16) float g_xa[N_NODES * HID];   // x @ W1[:64] + b1
__device__ __align__(16) float g_xb[N_NODES * HID];   // x @ W1[64:]
__device__ __align__(16) float g_eb[N_EDGES * HID];   // segment sums of xb
__device__ int      g_cnt[N_EDGES];
__device__ int      g_start[N_EDGES];
__device__ int      g_cursor[N_EDGES];
__device__ int      g_adj[NNZ];      // node id per CSR slot
__device__ int      g_aidx[NNZ];     // original nnz index per CSR slot
__device__ float    g_sum_p[N_EDGES];
__device__ float    g_sum_s[N_EDGES];
__device__ int      g_cand[NNZ];
__device__ int      g_ncand;
__device__ int      g_total;
__device__ unsigned g_hist[5][2048];
__device__ Ctrl     g_ctrl;

// ---------------- zero the small scratch ----------------
__global__ void k_init() {
    int tid = blockIdx.x * blockDim.x + threadIdx.x;
    int nt  = gridDim.x * blockDim.x;
    for (int i = tid; i < N_EDGES; i += nt) { g_cnt[i] = 0; g_sum_s[i] = 0.0f; }
    for (int i = tid; i < 5 * 2048; i += nt) ((unsigned*)g_hist)[i] = 0u;
    if (tid == 0) {
        g_ctrl.p1 = 0; g_ctrl.p2 = 0; g_ctrl.Tbits = 0;
        g_ctrl.rank = 0; g_ctrl.skip = 0; g_ctrl.ib = 0; g_ctrl.cutoff = 0;
        g_ncand = 0; g_total = 0;
    }
}

// ---------------- per-node projections: xa = x@W1a + b1, xb = x@W1b ----------------
__global__ void k_proj(const float* __restrict__ x,
                       const float* __restrict__ W1,
                       const float* __restrict__ b1) {
    __shared__ float sW[128 * 32];
    for (int i = threadIdx.x; i < 128 * 32; i += blockDim.x) sW[i] = W1[i];
    __syncthreads();
    int lane = threadIdx.x & 31;
    int warp = threadIdx.x >> 5;
    int wpb  = blockDim.x >> 5;
    float bb = b1[lane];
    for (int row = blockIdx.x * wpb + warp; row < N_NODES; row += gridDim.x * wpb) {
        float x0 = x[row * 64 + lane];
        float x1 = x[row * 64 + 32 + lane];
        float aa = bb, ab = 0.0f;
#pragma unroll
        for (int k = 0; k < 32; k++) {
            float xv = __shfl_sync(0xffffffffu, x0, k);
            aa += xv * sW[k * 32 + lane];
            ab += xv * sW[(64 + k) * 32 + lane];
        }
#pragma unroll
        for (int k = 0; k < 32; k++) {
            float xv = __shfl_sync(0xffffffffu, x1, k);
            aa += xv * sW[(32 + k) * 32 + lane];
            ab += xv * sW[(96 + k) * 32 + lane];
        }
        g_xa[row * 32 + lane] = aa;
        g_xb[row * 32 + lane] = ab;
    }
}

// ---------------- CSR build ----------------
__global__ void k_count(const int* __restrict__ E) {
    int i = blockIdx.x * blockDim.x + threadIdx.x;
    if (i < NNZ) atomicAdd(&g_cnt[E[i]], 1);
}

__global__ void k_offsets() {
    int e = blockIdx.x * blockDim.x + threadIdx.x;
    int lane = threadIdx.x & 31;
    int c = (e < N_EDGES) ? g_cnt[e] : 0;
    // warp inclusive scan
    int pre = c;
#pragma unroll
    for (int off = 1; off < 32; off <<= 1) {
        int n = __shfl_up_sync(0xffffffffu, pre, off);
        if (lane >= off) pre += n;
    }
    int excl = pre - c;
    int tot  = __shfl_sync(0xffffffffu, pre, 31);
    int base = 0;
    if (lane == 31) base = atomicAdd(&g_total, tot);
    base = __shfl_sync(0xffffffffu, base, 31);
    if (e < N_EDGES) {
        g_start[e]  = base + excl;
        g_cursor[e] = base + excl;
    }
}

__global__ void k_fill(const int* __restrict__ V, const int* __restrict__ E) {
    int i = blockIdx.x * blockDim.x + threadIdx.x;
    if (i >= NNZ) return;
    int e = E[i];
    int pos = atomicAdd(&g_cursor[e], 1);
    g_adj[pos]  = V[i];
    g_aidx[pos] = i;
}

// ---------------- edge-major scatter: per-edge sums of xb, no atomics ----------------
__global__ void k_escatter() {
    int e = blockIdx.x * (blockDim.x >> 5) + (threadIdx.x >> 5);
    if (e >= N_EDGES) return;
    int lane = threadIdx.x & 31;
    int sub  = lane >> 3;     // member slot 0..3
    int q    = lane & 7;      // dim quadruple 0..7
    int start = g_start[e], d = g_cnt[e];
    float4 acc = make_float4(0.f, 0.f, 0.f, 0.f);
    for (int j = sub; j < d; j += 4) {
        int v = g_adj[start + j];
        float4 t = *reinterpret_cast<const float4*>(&g_xb[v * 32 + q * 4]);
        acc.x += t.x; acc.y += t.y; acc.z += t.z; acc.w += t.w;
    }
    // reduce across the 4 member slots (xor 8, 16)
#pragma unroll
    for (int off = 8; off <= 16; off <<= 1) {
        acc.x += __shfl_xor_sync(0xffffffffu, acc.x, off);
        acc.y += __shfl_xor_sync(0xffffffffu, acc.y, off);
        acc.z += __shfl_xor_sync(0xffffffffu, acc.z, off);
        acc.w += __shfl_xor_sync(0xffffffffu, acc.w, off);
    }
    if (lane < 8)
        reinterpret_cast<float4*>(&g_eb[e * 32])[lane] = acc;
}

// ---------------- edge-major MLP: probs + per-edge prob sums + phase0 hist ----------------
__global__ void k_elogits(const float* __restrict__ W2, const float* __restrict__ b2,
                          float* __restrict__ out_probs) {
    __shared__ unsigned sh[2048];
    for (int i = threadIdx.x; i < 2048; i += blockDim.x) sh[i] = 0u;
    __syncthreads();

    int e = blockIdx.x * (blockDim.x >> 5) + (threadIdx.x >> 5);
    int lane = threadIdx.x & 31;
    if (e < N_EDGES) {
        int sub = lane >> 3, q = lane & 7;
        int start = g_start[e], d = g_cnt[e];
        float ic = 1.0f / (float)(d > 1 ? d : 1);
        float4 m = reinterpret_cast<const float4*>(&g_eb[e * 32])[q];
        m.x *= ic; m.y *= ic; m.z *= ic; m.w *= ic;
        float4 w = reinterpret_cast<const float4*>(W2)[q];
        float b2v = b2[0];
        float psum = 0.0f;
        int nch = (d + 3) >> 2;
        for (int c = 0; c < nch; c++) {
            int j = c * 4 + sub;
            bool act = (j < d);
            float part = 0.0f;
            int ai = 0;
            if (act) {
                int v = g_adj[start + j];
                ai = g_aidx[start + j];
                float4 a = reinterpret_cast<const float4*>(&g_xa[v * 32])[q];
                float h0 = fmaxf(a.x + m.x, 0.0f);
                float h1 = fmaxf(a.y + m.y, 0.0f);
                float h2 = fmaxf(a.z + m.z, 0.0f);
                float h3 = fmaxf(a.w + m.w, 0.0f);
                part = h0 * w.x + h1 * w.y + h2 * w.z + h3 * w.w;
            }
            part += __shfl_xor_sync(0xffffffffu, part, 4);
            part += __shfl_xor_sync(0xffffffffu, part, 2);
            part += __shfl_xor_sync(0xffffffffu, part, 1);
            if (act && q == 0) {
                float z = part + b2v;
                float p = 1.0f / (1.0f + expf(-z));
                out_probs[ai] = p;
                psum += p;
                atomicAdd(&sh[__float_as_uint(p) >> 21], 1u);
            }
        }
        // reduce psum across lanes 0,8,16,24
        psum += __shfl_xor_sync(0xffffffffu, psum, 8);
        psum += __shfl_xor_sync(0xffffffffu, psum, 16);
        if (lane == 0) g_sum_p[e] = psum;
    }
    __syncthreads();
    for (int i = threadIdx.x; i < 2048; i += blockDim.x) {
        unsigned vv = sh[i];
        if (vv) atomicAdd(&g_hist[0][i], vv);
    }
}

// ---------------- compaction: collect phase-1 candidates + phase-1 hist ----------------
__global__ void k_compact(const float* __restrict__ probs) {
    __shared__ unsigned sh[2048];
    for (int i = threadIdx.x; i < 2048; i += blockDim.x) sh[i] = 0u;
    __syncthreads();
    unsigned p1 = g_ctrl.p1;
    int tid = blockIdx.x * blockDim.x + threadIdx.x;
    int nt  = gridDim.x * blockDim.x;
    int iters = (NNZ + nt - 1) / nt;
    int lane = threadIdx.x & 31;
    for (int it = 0; it < iters; it++) {
        int i = tid + it * nt;
        bool mt = false;
        unsigned bits = 0;
        if (i < NNZ) {
            bits = __float_as_uint(probs[i]);
            mt = ((bits >> 21) == p1);
        }
        unsigned ball = __ballot_sync(0xffffffffu, mt);
        if (ball) {
            int cnt = __popc(ball);
            int base = 0;
            if (lane == 0) base = atomicAdd(&g_ncand, cnt);
            base = __shfl_sync(0xffffffffu, base, 0);
            if (mt) {
                int off = __popc(ball & ((1u << lane) - 1u));
                g_cand[base + off] = i;
                atomicAdd(&sh[(bits >> 10) & 2047u], 1u);
            }
        }
    }
    __syncthreads();
    for (int i = threadIdx.x; i < 2048; i += blockDim.x) {
        unsigned vv = sh[i];
        if (vv) atomicAdd(&g_hist[1][i], vv);
    }
}

// ---------------- candidate-domain histograms (phases 2..4) ----------------
__global__ void k_chist(const float* __restrict__ probs, int phase) {
    __shared__ unsigned sh[2048];
    for (int i = threadIdx.x; i < 2048; i += blockDim.x) sh[i] = 0u;
    __syncthreads();
    if (phase >= 3 && g_ctrl.skip) return;
    unsigned p2 = g_ctrl.p2, Tb = g_ctrl.Tbits;
    int ib = g_ctrl.ib;
    int n  = g_ncand;
    int tid = blockIdx.x * blockDim.x + threadIdx.x;
    int nt  = gridDim.x * blockDim.x;
    for (int c = tid; c < n; c += nt) {
        int i = g_cand[c];
        unsigned bits = __float_as_uint(probs[i]);
        int b = -1;
        if (phase == 2)      { if ((bits >> 10) == p2) b = (int)(bits & 1023u); }
        else if (phase == 3) { if (bits == Tb) b = i >> 11; }
        else                 { if (bits == Tb && (i >> 11) == ib) b = i & 2047; }
        if (b >= 0) atomicAdd(&sh[b], 1u);
    }
    __syncthreads();
    for (int i = threadIdx.x; i < 2048; i += blockDim.x) {
        unsigned vv = sh[i];
        if (vv) atomicAdd(&g_hist[phase][i], vv);
    }
}

// ---------------- selection: scan + pick bucket ----------------
__global__ void k_scan(int phase) {
    __shared__ unsigned sA[2048], sB[2048];
    if (phase >= 3 && g_ctrl.skip) return;
    int n   = (phase == 2 || phase == 3) ? 1024 : 2048;
    int tid = threadIdx.x;  // blockDim = 1024
    const unsigned* hist = g_hist[phase];
    for (int i = tid; i < n; i += 1024) sA[i] = hist[i];
    __syncthreads();
    bool desc = (phase <= 2);
    unsigned *in = sA, *out = sB;
    for (int off = 1; off < n; off <<= 1) {
        for (int i = tid; i < n; i += 1024) {
            unsigned add = 0;
            if (desc) { if (i + off < n) add = in[i + off]; }
            else      { if (i >= off)    add = in[i - off]; }
            out[i] = in[i] + add;
        }
        __syncthreads();
        unsigned* t = in; in = out; out = t;
    }
    int rank = (phase == 0) ? K_KEEP : g_ctrl.rank;
    for (int i = tid; i < n; i += 1024) {
        bool hit;
        unsigned adj;
        if (desc) {
            unsigned nxt = (i + 1 < n) ? in[i + 1] : 0u;
            hit = ((int)in[i] >= rank) && ((int)nxt < rank);
            adj = nxt;
        } else {
            unsigned prv = (i > 0) ? in[i - 1] : 0u;
            hit = ((int)in[i] >= rank) && ((int)prv < rank);
            adj = prv;
        }
        if (hit) {
            if (phase == 0)      { g_ctrl.p1 = (unsigned)i; g_ctrl.rank = rank - (int)adj; }
            else if (phase == 1) { g_ctrl.p2 = (g_ctrl.p1 << 11) | (unsigned)i; g_ctrl.rank = rank - (int)adj; }
            else if (phase == 2) {
                g_ctrl.Tbits = (g_ctrl.p2 << 10) | (unsigned)i;
                int r   = rank - (int)adj;
                int neq = (int)(in[i] - adj);
                if (r >= neq) { g_ctrl.skip = 1; g_ctrl.cutoff = 0x7fffffff; }
                else          { g_ctrl.skip = 0; g_ctrl.rank = r; }
            }
            else if (phase == 3) { g_ctrl.ib = i; g_ctrl.rank = rank - (int)adj; }
            else                 { g_ctrl.cutoff = (g_ctrl.ib << 11) | i; }
        }
    }
}

// ---------------- hard/soft mask + edge soft sums ----------------
__global__ void k_mask(const int* __restrict__ E, const float* __restrict__ probs,
                       float* __restrict__ soft, float* __restrict__ hard) {
    int i = blockIdx.x * blockDim.x + threadIdx.x;
    if (i >= NNZ) return;
    float p = probs[i];
    unsigned bits = __float_as_uint(p);
    unsigned T = g_ctrl.Tbits;
    bool h = (bits > T) || (bits == T && i <= g_ctrl.cutoff);
    float hf = h ? 1.0f : 0.0f;
    float sf = h ? ((1.0f - p) + p) : 0.0f;   // straight-through forward value
    soft[i] = sf;
    hard[i] = hf;
    asm volatile("red.global.add.f32 [%0], %1;" :: "l"(&g_sum_s[E[i]]), "f"(sf) : "memory");
}

// ---------------- edge outputs ----------------
__global__ void k_edges(float* __restrict__ ep, float* __restrict__ es, float* __restrict__ eh) {
    int e = blockIdx.x * blockDim.x + threadIdx.x;
    if (e >= N_EDGES) return;
    int ci = g_cnt[e];
    float c = (float)(ci > 1 ? ci : 1);
    float ss = g_sum_s[e];
    ep[e] = g_sum_p[e] / c;
    es[e] = ss / c;
    eh[e] = (ss > 0.0f) ? 1.0f : 0.0f;
}

// ---------------- launcher ----------------
extern "C" void kernel_launch(void* const* d_in, const int* in_sizes, int n_in,
                              void* d_out, int out_size) {
    const float* x  = (const float*)d_in[0];
    const int*   V  = (const int*)d_in[1];
    const int*   E  = (const int*)d_in[2];
    const float* W1 = (const float*)d_in[3];
    const float* b1 = (const float*)d_in[4];
    const float* W2 = (const float*)d_in[5];
    const float* b2 = (const float*)d_in[6];

    float* out   = (float*)d_out;
    float* probs = out;
    float* soft  = out + NNZ;
    float* hard  = out + 2 * NNZ;
    float* ep    = out + 3 * NNZ;
    float* es    = ep + N_EDGES;
    float* eh    = es + N_EDGES;

    const int NB_NNZ  = (NNZ + 255) / 256;
    const int NB_EDGE = (N_EDGES + 255) / 256;
    const int NB_WARP = N_EDGES / 8;           // 1 warp per edge, 8 warps/block

    k_init<<<512, 256>>>();
    k_proj<<<512, 256>>>(x, W1, b1);
    k_count<<<NB_NNZ, 256>>>(E);
    k_offsets<<<NB_EDGE, 256>>>();
    k_fill<<<NB_NNZ, 256>>>(V, E);
    k_escatter<<<NB_WARP, 256>>>();
    k_elogits<<<NB_WARP, 256>>>(W2, b2, probs);
    k_scan<<<1, 1024>>>(0);
    k_compact<<<512, 256>>>(probs);
    k_scan<<<1, 1024>>>(1);
    k_chist<<<256, 256>>>(probs, 2);
    k_scan<<<1, 1024>>>(2);
    k_chist<<<256, 256>>>(probs, 3);
    k_scan<<<1, 1024>>>(3);
    k_chist<<<256, 256>>>(probs, 4);
    k_scan<<<1, 1024>>>(4);
    k_mask<<<NB_NNZ, 256>>>(E, probs, soft, hard);
    k_edges<<<NB_EDGE, 256>>>(ep, es, eh);
}

// round 3
// speedup vs baseline: 1.1543x; 1.1543x over previous
#include <cuda_runtime.h>
#include <cstdint>
#include <math.h>

#define N_NODES   100000
#define N_EDGES   200000
#define NNZ       2000000
#define DIM       64
#define HID       32
#define K_KEEP    1000000

// ---------------- device scratch (no allocations allowed) ----------------
struct Ctrl {
    unsigned p1, p2, Tbits;
    int rank;
    int skip;
    int ib;
    int cutoff;
};

__device__ __align__(16) float g_xa[N_NODES * HID];   // x @ W1[:64] + b1
__device__ __align__(16) float g_xb[N_NODES * HID];   // x @ W1[64:]
__device__ __align__(16) float g_eb[N_EDGES * HID];   // segment sums of xb
__device__ int      g_cnt[N_EDGES];
__device__ float    g_sum_p[N_EDGES];
__device__ float    g_sum_s[N_EDGES];
__device__ int      g_cand[NNZ];
__device__ unsigned g_cbits[NNZ];
__device__ int      g_ncand;
__device__ unsigned g_hist[5][2048];
__device__ Ctrl     g_ctrl;

// ---------------- zero scratch (vectorized) ----------------
__global__ void k_zero() {
    int tid = blockIdx.x * blockDim.x + threadIdx.x;
    int nt  = gridDim.x * blockDim.x;
    float4 z4 = make_float4(0.f, 0.f, 0.f, 0.f);
    float4* eb4 = reinterpret_cast<float4*>(g_eb);
    for (int i = tid; i < N_EDGES * HID / 4; i += nt) eb4[i] = z4;
    for (int i = tid; i < N_EDGES; i += nt) {
        g_cnt[i] = 0; g_sum_p[i] = 0.0f; g_sum_s[i] = 0.0f;
    }
    for (int i = tid; i < 5 * 2048; i += nt) ((unsigned*)g_hist)[i] = 0u;
    if (tid == 0) {
        g_ctrl.p1 = 0; g_ctrl.p2 = 0; g_ctrl.Tbits = 0;
        g_ctrl.rank = 0; g_ctrl.skip = 0; g_ctrl.ib = 0; g_ctrl.cutoff = 0;
        g_ncand = 0;
    }
}

// ---------------- per-node projections: xa = x@W1a + b1, xb = x@W1b ----------------
__global__ void k_proj(const float* __restrict__ x,
                       const float* __restrict__ W1,
                       const float* __restrict__ b1) {
    __shared__ float sW[128 * 32];
    for (int i = threadIdx.x; i < 128 * 32; i += blockDim.x) sW[i] = W1[i];
    __syncthreads();
    int lane = threadIdx.x & 31;
    int warp = threadIdx.x >> 5;
    int wpb  = blockDim.x >> 5;
    float bb = b1[lane];
    for (int row = blockIdx.x * wpb + warp; row < N_NODES; row += gridDim.x * wpb) {
        float x0 = x[row * 64 + lane];
        float x1 = x[row * 64 + 32 + lane];
        float aa = bb, ab = 0.0f;
#pragma unroll
        for (int k = 0; k < 32; k++) {
            float xv = __shfl_sync(0xffffffffu, x0, k);
            aa += xv * sW[k * 32 + lane];
            ab += xv * sW[(64 + k) * 32 + lane];
        }
#pragma unroll
        for (int k = 0; k < 32; k++) {
            float xv = __shfl_sync(0xffffffffu, x1, k);
            aa += xv * sW[(32 + k) * 32 + lane];
            ab += xv * sW[(96 + k) * 32 + lane];
        }
        g_xa[row * 32 + lane] = aa;
        g_xb[row * 32 + lane] = ab;
    }
}

// ---------------- scatter xb into per-edge sums (v4 reductions) ----------------
__global__ void k_scatter(const int* __restrict__ V, const int* __restrict__ E) {
    int tid = blockIdx.x * blockDim.x + threadIdx.x;
    int g   = tid >> 3;
    int sub = tid & 7;
    if (g >= NNZ) return;
    int v = V[g], e = E[g];
    float4 val = *reinterpret_cast<const float4*>(&g_xb[v * 32 + sub * 4]);
    float* dst = &g_eb[e * 32 + sub * 4];
    asm volatile("red.global.add.v4.f32 [%0], {%1,%2,%3,%4};"
                 :: "l"(dst), "f"(val.x), "f"(val.y), "f"(val.z), "f"(val.w)
                 : "memory");
    if (sub == 0) atomicAdd(&g_cnt[e], 1);
}

// ---------------- fused MLP: probs + edge prob sums + phase-0 histogram ----------------
__global__ void k_logits(const int* __restrict__ V, const int* __restrict__ E,
                         const float* __restrict__ W2, const float* __restrict__ b2,
                         float* __restrict__ out_probs) {
    __shared__ unsigned sh[2048];
    for (int i = threadIdx.x; i < 2048; i += blockDim.x) sh[i] = 0u;
    __syncthreads();

    int tid = blockIdx.x * blockDim.x + threadIdx.x;
    int sub = tid & 7;
    int g0  = tid >> 3;
    int stride_g = (gridDim.x * blockDim.x) >> 3;
    int iters = (NNZ + stride_g - 1) / stride_g;
    float b2v = b2[0];
    float4 w = reinterpret_cast<const float4*>(W2)[sub];

    for (int it = 0; it < iters; it++) {
        int g = g0 + it * stride_g;
        bool act = (g < NNZ);
        float part = 0.0f;
        int e = 0;
        if (act) {
            int v = V[g];
            e = E[g];
            int c = g_cnt[e];
            float ic = 1.0f / (float)(c > 1 ? c : 1);
            float4 a = *reinterpret_cast<const float4*>(&g_xa[v * 32 + sub * 4]);
            float4 m = *reinterpret_cast<const float4*>(&g_eb[e * 32 + sub * 4]);
            float h0 = fmaxf(a.x + m.x * ic, 0.0f);
            float h1 = fmaxf(a.y + m.y * ic, 0.0f);
            float h2 = fmaxf(a.z + m.z * ic, 0.0f);
            float h3 = fmaxf(a.w + m.w * ic, 0.0f);
            part = h0 * w.x + h1 * w.y + h2 * w.z + h3 * w.w;
        }
        part += __shfl_xor_sync(0xffffffffu, part, 4);
        part += __shfl_xor_sync(0xffffffffu, part, 2);
        part += __shfl_xor_sync(0xffffffffu, part, 1);
        if (act && sub == 0) {
            float z = part + b2v;
            float p = 1.0f / (1.0f + expf(-z));
            out_probs[g] = p;
            atomicAdd(&sh[__float_as_uint(p) >> 21], 1u);
            asm volatile("red.global.add.f32 [%0], %1;" :: "l"(&g_sum_p[e]), "f"(p) : "memory");
        }
    }
    __syncthreads();
    for (int i = threadIdx.x; i < 2048; i += blockDim.x) {
        unsigned vv = sh[i];
        if (vv) atomicAdd(&g_hist[0][i], vv);
    }
}

// ---------------- compaction: collect phase-1 candidates + phase-1 hist ----------------
__global__ void k_compact(const float* __restrict__ probs) {
    __shared__ unsigned sh[2048];
    for (int i = threadIdx.x; i < 2048; i += blockDim.x) sh[i] = 0u;
    __syncthreads();
    unsigned p1 = g_ctrl.p1;
    int tid = blockIdx.x * blockDim.x + threadIdx.x;
    int nt  = gridDim.x * blockDim.x;
    int iters = (NNZ + nt - 1) / nt;
    int lane = threadIdx.x & 31;
    for (int it = 0; it < iters; it++) {
        int i = tid + it * nt;
        bool mt = false;
        unsigned bits = 0;
        if (i < NNZ) {
            bits = __float_as_uint(probs[i]);
            mt = ((bits >> 21) == p1);
        }
        unsigned ball = __ballot_sync(0xffffffffu, mt);
        if (ball) {
            int cnt = __popc(ball);
            int base = 0;
            if (lane == 0) base = atomicAdd(&g_ncand, cnt);
            base = __shfl_sync(0xffffffffu, base, 0);
            if (mt) {
                int off = __popc(ball & ((1u << lane) - 1u));
                g_cand[base + off]  = i;
                g_cbits[base + off] = bits;
                atomicAdd(&sh[(bits >> 10) & 2047u], 1u);
            }
        }
    }
    __syncthreads();
    for (int i = threadIdx.x; i < 2048; i += blockDim.x) {
        unsigned vv = sh[i];
        if (vv) atomicAdd(&g_hist[1][i], vv);
    }
}

// ---------------- candidate-domain histograms (phases 2..4) ----------------
__global__ void k_chist(int phase) {
    __shared__ unsigned sh[2048];
    for (int i = threadIdx.x; i < 2048; i += blockDim.x) sh[i] = 0u;
    __syncthreads();
    if (phase >= 3 && g_ctrl.skip) return;
    unsigned p2 = g_ctrl.p2, Tb = g_ctrl.Tbits;
    int ib = g_ctrl.ib;
    int n  = g_ncand;
    int tid = blockIdx.x * blockDim.x + threadIdx.x;
    int nt  = gridDim.x * blockDim.x;
    for (int c = tid; c < n; c += nt) {
        unsigned bits = g_cbits[c];
        int b = -1;
        if (phase == 2)      { if ((bits >> 10) == p2) b = (int)(bits & 1023u); }
        else if (phase == 3) { if (bits == Tb) b = g_cand[c] >> 11; }
        else                 { int i = g_cand[c];
                               if (bits == Tb && (i >> 11) == ib) b = i & 2047; }
        if (b >= 0) atomicAdd(&sh[b], 1u);
    }
    __syncthreads();
    for (int i = threadIdx.x; i < 2048; i += blockDim.x) {
        unsigned vv = sh[i];
        if (vv) atomicAdd(&g_hist[phase][i], vv);
    }
}

// ---------------- selection: scan + pick bucket ----------------
__global__ void k_scan(int phase) {
    __shared__ unsigned sA[2048], sB[2048];
    if (phase >= 3 && g_ctrl.skip) return;
    int n   = (phase == 2 || phase == 3) ? 1024 : 2048;
    int tid = threadIdx.x;  // blockDim = 1024
    const unsigned* hist = g_hist[phase];
    for (int i = tid; i < n; i += 1024) sA[i] = hist[i];
    __syncthreads();
    bool desc = (phase <= 2);
    unsigned *in = sA, *out = sB;
    for (int off = 1; off < n; off <<= 1) {
        for (int i = tid; i < n; i += 1024) {
            unsigned add = 0;
            if (desc) { if (i + off < n) add = in[i + off]; }
            else      { if (i >= off)    add = in[i - off]; }
            out[i] = in[i] + add;
        }
        __syncthreads();
        unsigned* t = in; in = out; out = t;
    }
    int rank = (phase == 0) ? K_KEEP : g_ctrl.rank;
    for (int i = tid; i < n; i += 1024) {
        bool hit;
        unsigned adj;
        if (desc) {
            unsigned nxt = (i + 1 < n) ? in[i + 1] : 0u;
            hit = ((int)in[i] >= rank) && ((int)nxt < rank);
            adj = nxt;
        } else {
            unsigned prv = (i > 0) ? in[i - 1] : 0u;
            hit = ((int)in[i] >= rank) && ((int)prv < rank);
            adj = prv;
        }
        if (hit) {
            if (phase == 0)      { g_ctrl.p1 = (unsigned)i; g_ctrl.rank = rank - (int)adj; }
            else if (phase == 1) { g_ctrl.p2 = (g_ctrl.p1 << 11) | (unsigned)i; g_ctrl.rank = rank - (int)adj; }
            else if (phase == 2) {
                g_ctrl.Tbits = (g_ctrl.p2 << 10) | (unsigned)i;
                int r   = rank - (int)adj;
                int neq = (int)(in[i] - adj);
                if (r >= neq) { g_ctrl.skip = 1; g_ctrl.cutoff = 0x7fffffff; }
                else          { g_ctrl.skip = 0; g_ctrl.rank = r; }
            }
            else if (phase == 3) { g_ctrl.ib = i; g_ctrl.rank = rank - (int)adj; }
            else                 { g_ctrl.cutoff = (g_ctrl.ib << 11) | i; }
        }
    }
}

// ---------------- hard/soft mask + edge soft sums (vectorized) ----------------
__global__ void k_mask(const int* __restrict__ E, const float* __restrict__ probs,
                       float* __restrict__ soft, float* __restrict__ hard) {
    int t = blockIdx.x * blockDim.x + threadIdx.x;
    if (t >= NNZ / 4) return;
    float4 p4 = reinterpret_cast<const float4*>(probs)[t];
    int4   e4 = reinterpret_cast<const int4*>(E)[t];
    unsigned T = g_ctrl.Tbits;
    int cut = g_ctrl.cutoff;
    int base = t * 4;
    float pv[4] = {p4.x, p4.y, p4.z, p4.w};
    int   ev[4] = {e4.x, e4.y, e4.z, e4.w};
    float sf[4], hf[4];
#pragma unroll
    for (int j = 0; j < 4; j++) {
        unsigned bits = __float_as_uint(pv[j]);
        bool h = (bits > T) || (bits == T && (base + j) <= cut);
        hf[j] = h ? 1.0f : 0.0f;
        sf[j] = h ? ((1.0f - pv[j]) + pv[j]) : 0.0f;
        if (h)
            asm volatile("red.global.add.f32 [%0], %1;"
                         :: "l"(&g_sum_s[ev[j]]), "f"(sf[j]) : "memory");
    }
    reinterpret_cast<float4*>(soft)[t] = make_float4(sf[0], sf[1], sf[2], sf[3]);
    reinterpret_cast<float4*>(hard)[t] = make_float4(hf[0], hf[1], hf[2], hf[3]);
}

// ---------------- edge outputs ----------------
__global__ void k_edges(float* __restrict__ ep, float* __restrict__ es, float* __restrict__ eh) {
    int e = blockIdx.x * blockDim.x + threadIdx.x;
    if (e >= N_EDGES) return;
    int ci = g_cnt[e];
    float c = (float)(ci > 1 ? ci : 1);
    float ss = g_sum_s[e];
    ep[e] = g_sum_p[e] / c;
    es[e] = ss / c;
    eh[e] = (ss > 0.0f) ? 1.0f : 0.0f;
}

// ---------------- launcher ----------------
extern "C" void kernel_launch(void* const* d_in, const int* in_sizes, int n_in,
                              void* d_out, int out_size) {
    const float* x  = (const float*)d_in[0];
    const int*   V  = (const int*)d_in[1];
    const int*   E  = (const int*)d_in[2];
    const float* W1 = (const float*)d_in[3];
    const float* b1 = (const float*)d_in[4];
    const float* W2 = (const float*)d_in[5];
    const float* b2 = (const float*)d_in[6];

    float* out   = (float*)d_out;
    float* probs = out;
    float* soft  = out + NNZ;
    float* hard  = out + 2 * NNZ;
    float* ep    = out + 3 * NNZ;
    float* es    = ep + N_EDGES;
    float* eh    = es + N_EDGES;

    k_zero<<<1024, 256>>>();
    k_proj<<<512, 256>>>(x, W1, b1);
    k_scatter<<<(NNZ * 8 + 255) / 256, 256>>>(V, E);
    k_logits<<<1024, 256>>>(V, E, W2, b2, probs);   // profiled slot
    k_scan<<<1, 1024>>>(0);
    k_compact<<<512, 256>>>(probs);
    k_scan<<<1, 1024>>>(1);
    k_chist<<<256, 256>>>(2);
    k_scan<<<1, 1024>>>(2);
    k_chist<<<256, 256>>>(3);
    k_scan<<<1, 1024>>>(3);
    k_chist<<<256, 256>>>(4);
    k_scan<<<1, 1024>>>(4);
    k_mask<<<(NNZ / 4 + 255) / 256, 256>>>(E, probs, soft, hard);
    k_edges<<<(N_EDGES + 255) / 256, 256>>>(ep, es, eh);
}

// round 4
// speedup vs baseline: 1.1685x; 1.0123x over previous
#include <cuda_runtime.h>
#include <cstdint>
#include <math.h>

#define N_NODES   100000
#define N_EDGES   200000
#define NNZ       2000000
#define DIM       64
#define HID       32
#define K_KEEP    1000000

// ---------------- device scratch (no allocations allowed) ----------------
struct Ctrl {
    unsigned p1, p2, Tbits;
    int rank;
    int skip;
    int ib;
    int cutoff;
};

__device__ __align__(16) float g_xa[N_NODES * HID];   // x @ W1[:64] + b1
__device__ __align__(16) float g_xb[N_NODES * HID];   // x @ W1[64:]
__device__ __align__(16) float g_eb[N_EDGES * HID];   // segment sums of xb
__device__ int      g_cnt[N_EDGES];
__device__ float    g_sum_p[N_EDGES];
__device__ float    g_sum_s[N_EDGES];
__device__ int      g_cand[NNZ];
__device__ unsigned g_cbits[NNZ];
__device__ int      g_ncand;
__device__ unsigned g_hist[5][2048];
__device__ Ctrl     g_ctrl;

// ---------------- zero the big accumulator (launch #1) ----------------
__global__ void k_zero_eb() {
    int tid = blockIdx.x * blockDim.x + threadIdx.x;
    int nt  = gridDim.x * blockDim.x;
    float4 z4 = make_float4(0.f, 0.f, 0.f, 0.f);
    float4* eb4 = reinterpret_cast<float4*>(g_eb);
    for (int i = tid; i < N_EDGES * HID / 4; i += nt) eb4[i] = z4;
}

// ---------------- zero small scratch (launch #3, shifts scatter to slot 4) ----------------
__global__ void k_zero_small() {
    int tid = blockIdx.x * blockDim.x + threadIdx.x;
    int nt  = gridDim.x * blockDim.x;
    for (int i = tid; i < N_EDGES; i += nt) {
        g_cnt[i] = 0; g_sum_p[i] = 0.0f; g_sum_s[i] = 0.0f;
    }
    for (int i = tid; i < 5 * 2048; i += nt) ((unsigned*)g_hist)[i] = 0u;
    if (tid == 0) {
        g_ctrl.p1 = 0; g_ctrl.p2 = 0; g_ctrl.Tbits = 0;
        g_ctrl.rank = 0; g_ctrl.skip = 0; g_ctrl.ib = 0; g_ctrl.cutoff = 0;
        g_ncand = 0;
    }
}

// ---------------- per-node projections: xa = x@W1a + b1, xb = x@W1b ----------------
__global__ void k_proj(const float* __restrict__ x,
                       const float* __restrict__ W1,
                       const float* __restrict__ b1) {
    __shared__ float sW[128 * 32];
    for (int i = threadIdx.x; i < 128 * 32; i += blockDim.x) sW[i] = W1[i];
    __syncthreads();
    int lane = threadIdx.x & 31;
    int warp = threadIdx.x >> 5;
    int wpb  = blockDim.x >> 5;
    float bb = b1[lane];
    for (int row = blockIdx.x * wpb + warp; row < N_NODES; row += gridDim.x * wpb) {
        float x0 = x[row * 64 + lane];
        float x1 = x[row * 64 + 32 + lane];
        float aa = bb, ab = 0.0f;
#pragma unroll
        for (int k = 0; k < 32; k++) {
            float xv = __shfl_sync(0xffffffffu, x0, k);
            aa += xv * sW[k * 32 + lane];
            ab += xv * sW[(64 + k) * 32 + lane];
        }
#pragma unroll
        for (int k = 0; k < 32; k++) {
            float xv = __shfl_sync(0xffffffffu, x1, k);
            aa += xv * sW[(32 + k) * 32 + lane];
            ab += xv * sW[(96 + k) * 32 + lane];
        }
        g_xa[row * 32 + lane] = aa;
        g_xb[row * 32 + lane] = ab;
    }
}

// ---------------- scatter xb into per-edge sums (v4 reductions) ----------------
__global__ void k_scatter(const int* __restrict__ V, const int* __restrict__ E) {
    int tid = blockIdx.x * blockDim.x + threadIdx.x;
    int g   = tid >> 3;
    int sub = tid & 7;
    if (g >= NNZ) return;
    int v = V[g], e = E[g];
    float4 val = *reinterpret_cast<const float4*>(&g_xb[v * 32 + sub * 4]);
    float* dst = &g_eb[e * 32 + sub * 4];
    asm volatile("red.global.add.v4.f32 [%0], {%1,%2,%3,%4};"
                 :: "l"(dst), "f"(val.x), "f"(val.y), "f"(val.z), "f"(val.w)
                 : "memory");
    if (sub == 0) atomicAdd(&g_cnt[e], 1);
}

// ---------------- fused MLP: probs + edge prob sums (one-shot) ----------------
__global__ void k_logits(const int* __restrict__ V, const int* __restrict__ E,
                         const float* __restrict__ W2, const float* __restrict__ b2,
                         float* __restrict__ out_probs) {
    int tid = blockIdx.x * blockDim.x + threadIdx.x;
    int g   = tid >> 3;
    int sub = tid & 7;
    if (g >= NNZ) return;
    int v = V[g], e = E[g];
    int c = g_cnt[e];
    float ic = 1.0f / (float)(c > 1 ? c : 1);
    float4 a  = *reinterpret_cast<const float4*>(&g_xa[v * 32 + sub * 4]);
    float4 m  = *reinterpret_cast<const float4*>(&g_eb[e * 32 + sub * 4]);
    float4 w  = *reinterpret_cast<const float4*>(&W2[sub * 4]);
    float h0 = fmaxf(a.x + m.x * ic, 0.0f);
    float h1 = fmaxf(a.y + m.y * ic, 0.0f);
    float h2 = fmaxf(a.z + m.z * ic, 0.0f);
    float h3 = fmaxf(a.w + m.w * ic, 0.0f);
    float part = h0 * w.x + h1 * w.y + h2 * w.z + h3 * w.w;
    part += __shfl_xor_sync(0xffffffffu, part, 4);
    part += __shfl_xor_sync(0xffffffffu, part, 2);
    part += __shfl_xor_sync(0xffffffffu, part, 1);
    if (sub == 0) {
        float z = part + b2[0];
        float p = 1.0f / (1.0f + __expf(-z));
        out_probs[g] = p;
        asm volatile("red.global.add.f32 [%0], %1;" :: "l"(&g_sum_p[e]), "f"(p) : "memory");
    }
}

// ---------------- phase-0 histogram (full probs) ----------------
__global__ void k_hist0(const float* __restrict__ probs) {
    __shared__ unsigned sh[2048];
    for (int i = threadIdx.x; i < 2048; i += blockDim.x) sh[i] = 0u;
    __syncthreads();
    int tid = blockIdx.x * blockDim.x + threadIdx.x;
    int nt  = gridDim.x * blockDim.x;
    for (int t = tid; t < NNZ / 4; t += nt) {
        float4 p4 = reinterpret_cast<const float4*>(probs)[t];
        atomicAdd(&sh[__float_as_uint(p4.x) >> 21], 1u);
        atomicAdd(&sh[__float_as_uint(p4.y) >> 21], 1u);
        atomicAdd(&sh[__float_as_uint(p4.z) >> 21], 1u);
        atomicAdd(&sh[__float_as_uint(p4.w) >> 21], 1u);
    }
    __syncthreads();
    for (int i = threadIdx.x; i < 2048; i += blockDim.x) {
        unsigned vv = sh[i];
        if (vv) atomicAdd(&g_hist[0][i], vv);
    }
}

// ---------------- compaction: collect phase-1 candidates + phase-1 hist ----------------
__global__ void k_compact(const float* __restrict__ probs) {
    __shared__ unsigned sh[2048];
    for (int i = threadIdx.x; i < 2048; i += blockDim.x) sh[i] = 0u;
    __syncthreads();
    unsigned p1 = g_ctrl.p1;
    int tid = blockIdx.x * blockDim.x + threadIdx.x;
    int nt  = gridDim.x * blockDim.x;
    int iters = (NNZ + nt - 1) / nt;
    int lane = threadIdx.x & 31;
    for (int it = 0; it < iters; it++) {
        int i = tid + it * nt;
        bool mt = false;
        unsigned bits = 0;
        if (i < NNZ) {
            bits = __float_as_uint(probs[i]);
            mt = ((bits >> 21) == p1);
        }
        unsigned ball = __ballot_sync(0xffffffffu, mt);
        if (ball) {
            int cnt = __popc(ball);
            int base = 0;
            if (lane == 0) base = atomicAdd(&g_ncand, cnt);
            base = __shfl_sync(0xffffffffu, base, 0);
            if (mt) {
                int off = __popc(ball & ((1u << lane) - 1u));
                g_cand[base + off]  = i;
                g_cbits[base + off] = bits;
                atomicAdd(&sh[(bits >> 10) & 2047u], 1u);
            }
        }
    }
    __syncthreads();
    for (int i = threadIdx.x; i < 2048; i += blockDim.x) {
        unsigned vv = sh[i];
        if (vv) atomicAdd(&g_hist[1][i], vv);
    }
}

// ---------------- candidate-domain histograms (phases 2..4) ----------------
__global__ void k_chist(int phase) {
    __shared__ unsigned sh[2048];
    for (int i = threadIdx.x; i < 2048; i += blockDim.x) sh[i] = 0u;
    __syncthreads();
    if (phase >= 3 && g_ctrl.skip) return;
    unsigned p2 = g_ctrl.p2, Tb = g_ctrl.Tbits;
    int ib = g_ctrl.ib;
    int n  = g_ncand;
    int tid = blockIdx.x * blockDim.x + threadIdx.x;
    int nt  = gridDim.x * blockDim.x;
    for (int c = tid; c < n; c += nt) {
        unsigned bits = g_cbits[c];
        int b = -1;
        if (phase == 2)      { if ((bits >> 10) == p2) b = (int)(bits & 1023u); }
        else if (phase == 3) { if (bits == Tb) b = g_cand[c] >> 11; }
        else                 { int i = g_cand[c];
                               if (bits == Tb && (i >> 11) == ib) b = i & 2047; }
        if (b >= 0) atomicAdd(&sh[b], 1u);
    }
    __syncthreads();
    for (int i = threadIdx.x; i < 2048; i += blockDim.x) {
        unsigned vv = sh[i];
        if (vv) atomicAdd(&g_hist[phase][i], vv);
    }
}

// ---------------- selection: scan + pick bucket ----------------
__global__ void k_scan(int phase) {
    __shared__ unsigned sA[2048], sB[2048];
    if (phase >= 3 && g_ctrl.skip) return;
    int n   = (phase == 2 || phase == 3) ? 1024 : 2048;
    int tid = threadIdx.x;  // blockDim = 1024
    const unsigned* hist = g_hist[phase];
    for (int i = tid; i < n; i += 1024) sA[i] = hist[i];
    __syncthreads();
    bool desc = (phase <= 2);
    unsigned *in = sA, *out = sB;
    for (int off = 1; off < n; off <<= 1) {
        for (int i = tid; i < n; i += 1024) {
            unsigned add = 0;
            if (desc) { if (i + off < n) add = in[i + off]; }
            else      { if (i >= off)    add = in[i - off]; }
            out[i] = in[i] + add;
        }
        __syncthreads();
        unsigned* t = in; in = out; out = t;
    }
    int rank = (phase == 0) ? K_KEEP : g_ctrl.rank;
    for (int i = tid; i < n; i += 1024) {
        bool hit;
        unsigned adj;
        if (desc) {
            unsigned nxt = (i + 1 < n) ? in[i + 1] : 0u;
            hit = ((int)in[i] >= rank) && ((int)nxt < rank);
            adj = nxt;
        } else {
            unsigned prv = (i > 0) ? in[i - 1] : 0u;
            hit = ((int)in[i] >= rank) && ((int)prv < rank);
            adj = prv;
        }
        if (hit) {
            if (phase == 0)      { g_ctrl.p1 = (unsigned)i; g_ctrl.rank = rank - (int)adj; }
            else if (phase == 1) { g_ctrl.p2 = (g_ctrl.p1 << 11) | (unsigned)i; g_ctrl.rank = rank - (int)adj; }
            else if (phase == 2) {
                g_ctrl.Tbits = (g_ctrl.p2 << 10) | (unsigned)i;
                int r   = rank - (int)adj;
                int neq = (int)(in[i] - adj);
                if (r >= neq) { g_ctrl.skip = 1; g_ctrl.cutoff = 0x7fffffff; }
                else          { g_ctrl.skip = 0; g_ctrl.rank = r; }
            }
            else if (phase == 3) { g_ctrl.ib = i; g_ctrl.rank = rank - (int)adj; }
            else                 { g_ctrl.cutoff = (g_ctrl.ib << 11) | i; }
        }
    }
}

// ---------------- hard/soft mask + edge soft sums (vectorized) ----------------
__global__ void k_mask(const int* __restrict__ E, const float* __restrict__ probs,
                       float* __restrict__ soft, float* __restrict__ hard) {
    int t = blockIdx.x * blockDim.x + threadIdx.x;
    if (t >= NNZ / 4) return;
    float4 p4 = reinterpret_cast<const float4*>(probs)[t];
    int4   e4 = reinterpret_cast<const int4*>(E)[t];
    unsigned T = g_ctrl.Tbits;
    int cut = g_ctrl.cutoff;
    int base = t * 4;
    float pv[4] = {p4.x, p4.y, p4.z, p4.w};
    int   ev[4] = {e4.x, e4.y, e4.z, e4.w};
    float sf[4], hf[4];
#pragma unroll
    for (int j = 0; j < 4; j++) {
        unsigned bits = __float_as_uint(pv[j]);
        bool h = (bits > T) || (bits == T && (base + j) <= cut);
        hf[j] = h ? 1.0f : 0.0f;
        sf[j] = h ? ((1.0f - pv[j]) + pv[j]) : 0.0f;
        if (h)
            asm volatile("red.global.add.f32 [%0], %1;"
                         :: "l"(&g_sum_s[ev[j]]), "f"(sf[j]) : "memory");
    }
    reinterpret_cast<float4*>(soft)[t] = make_float4(sf[0], sf[1], sf[2], sf[3]);
    reinterpret_cast<float4*>(hard)[t] = make_float4(hf[0], hf[1], hf[2], hf[3]);
}

// ---------------- edge outputs ----------------
__global__ void k_edges(float* __restrict__ ep, float* __restrict__ es, float* __restrict__ eh) {
    int e = blockIdx.x * blockDim.x + threadIdx.x;
    if (e >= N_EDGES) return;
    int ci = g_cnt[e];
    float c = (float)(ci > 1 ? ci : 1);
    float ss = g_sum_s[e];
    ep[e] = g_sum_p[e] / c;
    es[e] = ss / c;
    eh[e] = (ss > 0.0f) ? 1.0f : 0.0f;
}

// ---------------- launcher ----------------
extern "C" void kernel_launch(void* const* d_in, const int* in_sizes, int n_in,
                              void* d_out, int out_size) {
    const float* x  = (const float*)d_in[0];
    const int*   V  = (const int*)d_in[1];
    const int*   E  = (const int*)d_in[2];
    const float* W1 = (const float*)d_in[3];
    const float* b1 = (const float*)d_in[4];
    const float* W2 = (const float*)d_in[5];
    const float* b2 = (const float*)d_in[6];

    float* out   = (float*)d_out;
    float* probs = out;
    float* soft  = out + NNZ;
    float* hard  = out + 2 * NNZ;
    float* ep    = out + 3 * NNZ;
    float* es    = ep + N_EDGES;
    float* eh    = es + N_EDGES;

    k_zero_eb<<<512, 256>>>();                          // #1
    k_proj<<<512, 256>>>(x, W1, b1);                    // #2
    k_zero_small<<<256, 256>>>();                       // #3
    k_scatter<<<(NNZ * 8 + 255) / 256, 256>>>(V, E);    // #4  <- profiled slot
    k_logits<<<(NNZ * 8 + 255) / 256, 256>>>(V, E, W2, b2, probs);
    k_hist0<<<512, 256>>>(probs);
    k_scan<<<1, 1024>>>(0);
    k_compact<<<512, 256>>>(probs);
    k_scan<<<1, 1024>>>(1);
    k_chist<<<256, 256>>>(2);
    k_scan<<<1, 1024>>>(2);
    k_chist<<<256, 256>>>(3);
    k_scan<<<1, 1024>>>(3);
    k_chist<<<256, 256>>>(4);
    k_scan<<<1, 1024>>>(4);
    k_mask<<<(NNZ / 4 + 255) / 256, 256>>>(E, probs, soft, hard);
    k_edges<<<(N_EDGES + 255) / 256, 256>>>(ep, es, eh);
}